// round 7
// baseline (speedup 1.0000x reference)
#include <cuda_runtime.h>

#define DIM 128
#define MAXN 50000

// Scratch for h = X @ W^T  (allocation-free scratch per harness rules)
__device__ float g_h[(size_t)MAXN * DIM];

// ---------------------------------------------------------------------------
// GEMM: h[n, o] = sum_k X[n, k] * W[o, k]
// Block = 256 threads (8 warps). Each warp computes 8 rows x 128 cols.
// W transposed into smem WT[k][o] pad 132 (conflict-free LDS.128 on read).
// ---------------------------------------------------------------------------
__global__ void gemm_kernel(const float* __restrict__ X,
                            const float* __restrict__ W,
                            int n_rows) {
    extern __shared__ float sm[];
    float* WT = sm;                    // 128 * 132 floats
    float* xr = sm + 128 * 132;        // 8 warps * 8 rows * 128 floats

    for (int i = threadIdx.x; i < DIM * DIM; i += blockDim.x) {
        int o = i >> 7;
        int k = i & 127;
        WT[k * 132 + o] = W[i];
    }
    __syncthreads();

    const int warp = threadIdx.x >> 5;
    const int lane = threadIdx.x & 31;
    const int nwarps = blockDim.x >> 5;
    const int gw = blockIdx.x * nwarps + warp;
    const int gstride = gridDim.x * nwarps;
    float* xw = xr + warp * (8 * DIM);

    for (int base = gw * 8; base < n_rows; base += gstride * 8) {
        // Stage 8 rows of X into smem (float4 per lane = 512B per row)
#pragma unroll
        for (int r = 0; r < 8; r++) {
            int n = base + r;
            float4 v = make_float4(0.f, 0.f, 0.f, 0.f);
            if (n < n_rows) v = ((const float4*)X)[(size_t)n * 32 + lane];
            ((float4*)(xw + r * DIM))[lane] = v;
        }
        __syncwarp();

        float4 acc[8];
#pragma unroll
        for (int r = 0; r < 8; r++) acc[r] = make_float4(0.f, 0.f, 0.f, 0.f);

#pragma unroll 4
        for (int k = 0; k < DIM; k++) {
            float4 w = *(const float4*)(WT + k * 132 + lane * 4);
#pragma unroll
            for (int r = 0; r < 8; r++) {
                float x = xw[r * DIM + k];          // smem broadcast
                acc[r].x = fmaf(x, w.x, acc[r].x);
                acc[r].y = fmaf(x, w.y, acc[r].y);
                acc[r].z = fmaf(x, w.z, acc[r].z);
                acc[r].w = fmaf(x, w.w, acc[r].w);
            }
        }

#pragma unroll
        for (int r = 0; r < 8; r++) {
            int n = base + r;
            if (n < n_rows)
                ((float4*)g_h)[(size_t)n * 32 + lane] = acc[r];
        }
        __syncwarp();
    }
}

// ---------------------------------------------------------------------------
// Fused gated scatter over all G*E edges (persistent grid):
//   out[row] += sigmoid(alpha[g]) * val * h[col]
// Warp-per-edge-pair: 2 edges in flight per warp (MLP=2 on the L2 gather),
// one red.global.add.v4.f32 per lane per edge (16B payload, 512B per edge).
// Edge metadata loaded as int2/float2 (e0 always even -> 8B aligned).
// g computed via a bounded subtract loop (G is tiny) — no integer division.
// ---------------------------------------------------------------------------
__global__ void __launch_bounds__(256, 8)
scatter_kernel(const int* __restrict__ rows,
               const int* __restrict__ cols,
               const float* __restrict__ vals,
               const float* __restrict__ alpha,
               float* __restrict__ out,
               int E, int G, int total) {
    const int lane = threadIdx.x & 31;
    const int warp_global = blockIdx.x * (blockDim.x >> 5) + (threadIdx.x >> 5);
    const int nwarps_total = gridDim.x * (blockDim.x >> 5);

    for (int e0 = warp_global * 2; e0 < total; e0 += nwarps_total * 2) {
        // graph index for e0 (at most G-1 iterations, G ~ 3)
        int g0 = 0, rem = e0;
        while (rem >= E && g0 < G - 1) { rem -= E; g0++; }
        // e1 = e0 + 1: same graph unless rem == E-1
        int g1 = (rem == E - 1 && g0 < G - 1) ? g0 + 1 : g0;

        const bool have2 = (e0 + 1 < total);
        int2   rc, cc;
        float2 vv;
        if (have2) {
            rc = *(const int2*)(rows + e0);      // LDG.64 broadcast
            cc = *(const int2*)(cols + e0);
            vv = *(const float2*)(vals + e0);
        } else {
            rc.x = __ldg(rows + e0); rc.y = -1;
            cc.x = __ldg(cols + e0); cc.y = 0;
            vv.x = __ldg(vals + e0); vv.y = 0.f;
        }

        float a0 = __ldg(alpha + g0);
        float gate0 = 1.f / (1.f + __expf(-a0));
        float v0 = vv.x * gate0;
        float4 h0 = ((const float4*)g_h)[(size_t)cc.x * 32 + lane];

        float4 m1; int row1 = -1;
        if (have2) {
            float a1 = (g1 == g0) ? a0 : __ldg(alpha + g1);
            float gate1 = (g1 == g0) ? gate0 : (1.f / (1.f + __expf(-a1)));
            float v1 = vv.y * gate1;
            float4 h1 = ((const float4*)g_h)[(size_t)cc.y * 32 + lane];
            m1 = make_float4(v1 * h1.x, v1 * h1.y, v1 * h1.z, v1 * h1.w);
            row1 = rc.y;
        }

        {
            float* dst = out + (size_t)rc.x * DIM + (size_t)lane * 4;
            asm volatile("red.global.add.v4.f32 [%0], {%1, %2, %3, %4};"
                         :: "l"(dst),
                            "f"(v0 * h0.x), "f"(v0 * h0.y),
                            "f"(v0 * h0.z), "f"(v0 * h0.w)
                         : "memory");
        }
        if (row1 >= 0) {
            float* dst = out + (size_t)row1 * DIM + (size_t)lane * 4;
            asm volatile("red.global.add.v4.f32 [%0], {%1, %2, %3, %4};"
                         :: "l"(dst), "f"(m1.x), "f"(m1.y), "f"(m1.z), "f"(m1.w)
                         : "memory");
        }
    }
}

// ---------------------------------------------------------------------------
// Launch
// ---------------------------------------------------------------------------
extern "C" void kernel_launch(void* const* d_in, const int* in_sizes, int n_in,
                              void* d_out, int out_size) {
    const float* X     = (const float*)d_in[0];   // [N, 128]
    const float* W     = (const float*)d_in[1];   // [128, 128]
    const float* alpha = (const float*)d_in[2];   // [G, 1]
    const int*   rows  = (const int*)  d_in[3];   // [G, E]
    const int*   cols  = (const int*)  d_in[4];   // [G, E]
    const float* vals  = (const float*)d_in[5];   // [G, E]
    float* out = (float*)d_out;

    const int N = in_sizes[0] / DIM;
    const int G = in_sizes[2];
    const int E = in_sizes[3] / G;
    const int total = G * E;

    // Raise the dynamic smem cap BEFORE any launch (default 48KB; need ~98KB).
    const int smem_bytes = (128 * 132 + 8 * 8 * DIM) * (int)sizeof(float); // 100352
    cudaFuncSetAttribute(gemm_kernel,
                         cudaFuncAttributeMaxDynamicSharedMemorySize, smem_bytes);

    // Zero the poisoned output (scatter accumulates into it)
    cudaMemsetAsync(out, 0, (size_t)N * DIM * sizeof(float));

    // GEMM: 8 warps * 8 rows per 256-thread block, single pass
    int rows_per_block = 8 * 8;
    int gemm_grid = (N + rows_per_block - 1) / rows_per_block;
    if (gemm_grid < 1) gemm_grid = 1;
    gemm_kernel<<<gemm_grid, 256, smem_bytes>>>(X, W, N);

    // Scatter: persistent grid — 8 CTAs/SM (per launch_bounds) * 152 SMs max.
    int sc_grid = 152 * 8;
    int max_useful = (total + 15) / 16;   // 8 warps * 2 edges per step
    if (sc_grid > max_useful) sc_grid = max_useful;
    if (sc_grid < 1) sc_grid = 1;
    scatter_kernel<<<sc_grid, 256>>>(rows, cols, vals, alpha, out, E, G, total);
}

// round 8
// speedup vs baseline: 1.4547x; 1.4547x over previous
#include <cuda_runtime.h>

#define DIM  128
#define MAXN 50000
#define MAXT 4000000

// Scratch (allocation-free per harness rules)
__device__ float g_h[(size_t)MAXN * DIM];       // h = X @ W^T
__device__ int   g_count[MAXN];                 // per-row edge counts
__device__ int   g_start[MAXN + 1];             // CSR row starts (exclusive scan)
__device__ int   g_cursor[MAXN];                // scatter cursors (copy of starts)
__device__ int2  g_colval[MAXT];                // row-sorted (col, val*gate bits)

// ---------------------------------------------------------------------------
// GEMM: h[n, o] = sum_k X[n, k] * W[o, k]   (unchanged from R7 baseline)
// ---------------------------------------------------------------------------
__global__ void gemm_kernel(const float* __restrict__ X,
                            const float* __restrict__ W,
                            int n_rows) {
    extern __shared__ float sm[];
    float* WT = sm;                    // 128 * 132
    float* xr = sm + 128 * 132;        // 8 warps * 8 rows * 128

    for (int i = threadIdx.x; i < DIM * DIM; i += blockDim.x) {
        int o = i >> 7;
        int k = i & 127;
        WT[k * 132 + o] = W[i];
    }
    __syncthreads();

    const int warp = threadIdx.x >> 5;
    const int lane = threadIdx.x & 31;
    const int nwarps = blockDim.x >> 5;
    const int gw = blockIdx.x * nwarps + warp;
    const int gstride = gridDim.x * nwarps;
    float* xw = xr + warp * (8 * DIM);

    for (int base = gw * 8; base < n_rows; base += gstride * 8) {
#pragma unroll
        for (int r = 0; r < 8; r++) {
            int n = base + r;
            float4 v = make_float4(0.f, 0.f, 0.f, 0.f);
            if (n < n_rows) v = ((const float4*)X)[(size_t)n * 32 + lane];
            ((float4*)(xw + r * DIM))[lane] = v;
        }
        __syncwarp();

        float4 acc[8];
#pragma unroll
        for (int r = 0; r < 8; r++) acc[r] = make_float4(0.f, 0.f, 0.f, 0.f);

#pragma unroll 4
        for (int k = 0; k < DIM; k++) {
            float4 w = *(const float4*)(WT + k * 132 + lane * 4);
#pragma unroll
            for (int r = 0; r < 8; r++) {
                float x = xw[r * DIM + k];
                acc[r].x = fmaf(x, w.x, acc[r].x);
                acc[r].y = fmaf(x, w.y, acc[r].y);
                acc[r].z = fmaf(x, w.z, acc[r].z);
                acc[r].w = fmaf(x, w.w, acc[r].w);
            }
        }

#pragma unroll
        for (int r = 0; r < 8; r++) {
            int n = base + r;
            if (n < n_rows)
                ((float4*)g_h)[(size_t)n * 32 + lane] = acc[r];
        }
        __syncwarp();
    }
}

// ---------------------------------------------------------------------------
// 1) Histogram of destination rows
// ---------------------------------------------------------------------------
__global__ void hist_kernel(const int* __restrict__ rows, int total) {
    int i = blockIdx.x * blockDim.x + threadIdx.x;
    if (i < total) atomicAdd(&g_count[rows[i]], 1);
}

// ---------------------------------------------------------------------------
// 2) Exclusive scan of counts -> g_start, g_cursor (single block, 1024 thr,
//    4 elements per thread per chunk)
// ---------------------------------------------------------------------------
__global__ void scan_kernel(int n) {
    __shared__ int wsum[32];
    __shared__ int s_carry;
    const int tid = threadIdx.x, lane = tid & 31, wid = tid >> 5;
    int carry = 0;

    for (int base = 0; base < n; base += 4096) {
        int i0 = base + tid * 4;
        int4 c = make_int4(0, 0, 0, 0);
        if (i0 + 3 < n) {
            c = *(const int4*)(g_count + i0);
        } else {
            if (i0 + 0 < n) c.x = g_count[i0 + 0];
            if (i0 + 1 < n) c.y = g_count[i0 + 1];
            if (i0 + 2 < n) c.z = g_count[i0 + 2];
            if (i0 + 3 < n) c.w = g_count[i0 + 3];
        }
        int s = c.x + c.y + c.z + c.w;

        int v = s;
#pragma unroll
        for (int d = 1; d < 32; d <<= 1) {
            int t = __shfl_up_sync(0xffffffffu, v, d);
            if (lane >= d) v += t;
        }
        if (lane == 31) wsum[wid] = v;
        __syncthreads();
        if (wid == 0) {
            int w = wsum[lane];
#pragma unroll
            for (int d = 1; d < 32; d <<= 1) {
                int t = __shfl_up_sync(0xffffffffu, w, d);
                if (lane >= d) w += t;
            }
            wsum[lane] = w;
        }
        __syncthreads();

        int excl = v - s + (wid > 0 ? wsum[wid - 1] : 0) + carry;
        int4 o;
        o.x = excl;
        o.y = o.x + c.x;
        o.z = o.y + c.y;
        o.w = o.z + c.z;
        if (i0 + 3 < n) {
            *(int4*)(g_start  + i0) = o;
            *(int4*)(g_cursor + i0) = o;
        } else {
            if (i0 + 0 < n) { g_start[i0 + 0] = o.x; g_cursor[i0 + 0] = o.x; }
            if (i0 + 1 < n) { g_start[i0 + 1] = o.y; g_cursor[i0 + 1] = o.y; }
            if (i0 + 2 < n) { g_start[i0 + 2] = o.z; g_cursor[i0 + 2] = o.z; }
            if (i0 + 3 < n) { g_start[i0 + 3] = o.w; g_cursor[i0 + 3] = o.w; }
        }
        if (tid == 1023) s_carry = excl + s;
        __syncthreads();
        carry = s_carry;
        __syncthreads();   // protect wsum reuse next chunk
    }
    if (tid == 0) g_start[n] = carry;
}

// ---------------------------------------------------------------------------
// 3) Permute edges into row-sorted order, folding the sigmoid gate into val.
// ---------------------------------------------------------------------------
__global__ void permute_kernel(const int* __restrict__ rows,
                               const int* __restrict__ cols,
                               const float* __restrict__ vals,
                               const float* __restrict__ alpha,
                               int E, int G, int total) {
    int i = blockIdx.x * blockDim.x + threadIdx.x;
    if (i >= total) return;
    int g = 0, rem = i;
    while (rem >= E && g < G - 1) { rem -= E; g++; }
    float a = __ldg(alpha + g);
    float gate = 1.f / (1.f + __expf(-a));
    int row = __ldg(rows + i);
    int pos = atomicAdd(&g_cursor[row], 1);
    g_colval[pos] = make_int2(__ldg(cols + i),
                              __float_as_int(__ldg(vals + i) * gate));
}

// ---------------------------------------------------------------------------
// 4) Gather: one warp per row. 4 edges in flight (MLP=4 on the h[col] L2
//    gather), plain float4 store per lane at the end — no atomics.
// ---------------------------------------------------------------------------
__global__ void __launch_bounds__(256, 8)
gather_kernel(float* __restrict__ out, int N) {
    const int lane = threadIdx.x & 31;
    int w  = blockIdx.x * (blockDim.x >> 5) + (threadIdx.x >> 5);
    int nw = gridDim.x * (blockDim.x >> 5);

    for (int row = w; row < N; row += nw) {
        int s = g_start[row];
        int e = g_start[row + 1];
        float4 acc = make_float4(0.f, 0.f, 0.f, 0.f);

        int i = s;
        for (; i + 4 <= e; i += 4) {
            int2 cv0 = g_colval[i + 0];
            int2 cv1 = g_colval[i + 1];
            int2 cv2 = g_colval[i + 2];
            int2 cv3 = g_colval[i + 3];
            float4 h0 = ((const float4*)g_h)[(size_t)cv0.x * 32 + lane];
            float4 h1 = ((const float4*)g_h)[(size_t)cv1.x * 32 + lane];
            float4 h2 = ((const float4*)g_h)[(size_t)cv2.x * 32 + lane];
            float4 h3 = ((const float4*)g_h)[(size_t)cv3.x * 32 + lane];
            float v0 = __int_as_float(cv0.y);
            float v1 = __int_as_float(cv1.y);
            float v2 = __int_as_float(cv2.y);
            float v3 = __int_as_float(cv3.y);
            acc.x = fmaf(v0, h0.x, acc.x); acc.y = fmaf(v0, h0.y, acc.y);
            acc.z = fmaf(v0, h0.z, acc.z); acc.w = fmaf(v0, h0.w, acc.w);
            acc.x = fmaf(v1, h1.x, acc.x); acc.y = fmaf(v1, h1.y, acc.y);
            acc.z = fmaf(v1, h1.z, acc.z); acc.w = fmaf(v1, h1.w, acc.w);
            acc.x = fmaf(v2, h2.x, acc.x); acc.y = fmaf(v2, h2.y, acc.y);
            acc.z = fmaf(v2, h2.z, acc.z); acc.w = fmaf(v2, h2.w, acc.w);
            acc.x = fmaf(v3, h3.x, acc.x); acc.y = fmaf(v3, h3.y, acc.y);
            acc.z = fmaf(v3, h3.z, acc.z); acc.w = fmaf(v3, h3.w, acc.w);
        }
        for (; i < e; i++) {
            int2 cv = g_colval[i];
            float4 h = ((const float4*)g_h)[(size_t)cv.x * 32 + lane];
            float v = __int_as_float(cv.y);
            acc.x = fmaf(v, h.x, acc.x); acc.y = fmaf(v, h.y, acc.y);
            acc.z = fmaf(v, h.z, acc.z); acc.w = fmaf(v, h.w, acc.w);
        }

        ((float4*)out)[(size_t)row * 32 + lane] = acc;
    }
}

// ---------------------------------------------------------------------------
// Launch
// ---------------------------------------------------------------------------
extern "C" void kernel_launch(void* const* d_in, const int* in_sizes, int n_in,
                              void* d_out, int out_size) {
    const float* X     = (const float*)d_in[0];   // [N, 128]
    const float* W     = (const float*)d_in[1];   // [128, 128]
    const float* alpha = (const float*)d_in[2];   // [G, 1]
    const int*   rows  = (const int*)  d_in[3];   // [G, E]
    const int*   cols  = (const int*)  d_in[4];   // [G, E]
    const float* vals  = (const float*)d_in[5];   // [G, E]
    float* out = (float*)d_out;

    const int N = in_sizes[0] / DIM;
    const int G = in_sizes[2];
    const int E = in_sizes[3] / G;
    const int total = G * E;

    // Raise dynamic smem cap for the GEMM (default 48KB; need ~98KB).
    const int smem_bytes = (128 * 132 + 8 * 8 * DIM) * (int)sizeof(float);
    cudaFuncSetAttribute(gemm_kernel,
                         cudaFuncAttributeMaxDynamicSharedMemorySize, smem_bytes);

    // Zero the row-count histogram (device global; address via symbol lookup —
    // no allocation, capture-safe).
    void* cnt_ptr = nullptr;
    cudaGetSymbolAddress(&cnt_ptr, g_count);
    cudaMemsetAsync(cnt_ptr, 0, (size_t)N * sizeof(int));

    // GEMM: h = X @ W^T
    int gemm_grid = (N + 63) / 64;
    if (gemm_grid < 1) gemm_grid = 1;
    gemm_kernel<<<gemm_grid, 256, smem_bytes>>>(X, W, N);

    // CSR build: histogram -> scan -> permute
    int tblocks = (total + 255) / 256;
    hist_kernel<<<tblocks, 256>>>(rows, total);
    scan_kernel<<<1, 1024>>>(N);
    permute_kernel<<<tblocks, 256>>>(rows, cols, vals, alpha, E, G, total);

    // Gather: warp per row, persistent grid. Writes every output row (no memset).
    int ga_grid = 152 * 8;
    int max_useful = (N + 7) / 8;          // 8 warps per block
    if (ga_grid > max_useful) ga_grid = max_useful;
    if (ga_grid < 1) ga_grid = 1;
    gather_kernel<<<ga_grid, 256>>>(out, N);
}